// round 13
// baseline (speedup 1.0000x reference)
#include <cuda_runtime.h>
#include <cuda_bf16.h>
#include <math_constants.h>

// Problem constants (fixed shapes)
#define BB 64
#define LL 512
#define HH 768
#define TT 9
#define NROWS (BB * LL)
#define NPAIRS (NROWS / 2)   // 16384

#define NCH 8        // chunks per sequence
#define CHLEN 64     // steps per chunk

__device__ float g_llh[BB];
__device__ float g_logits_scratch[BB * LL * TT];   // fallback if out has no room

// ---------------------------------------------------------------------------
// Kernel A: logits = hidden @ W + b
// PERSISTENT blocks: grid 444 (3 CTAs/SM), W staged once per block, each warp
// grid-strides over row pairs (~4.6 each). R10's proven dataflow per pair:
// full float4 prefetch (12 LDG.128), scalar conflict-free W-LDS via swizzle
// Ws[9k + t + (k>>5)]. Rotated pipeline: next pair's LDGs issue before the
// current pair's reduce+store tail, so the tail hides DRAM latency.
// ---------------------------------------------------------------------------
__global__ __launch_bounds__(256, 3) void logits_kernel(
    const float* __restrict__ hidden,
    const float* __restrict__ W,
    const float* __restrict__ bias,
    float* __restrict__ logits)
{
    __shared__ float Ws[HH * TT + (HH >> 5)];   // 6936 floats = 27744 B
    __shared__ float bs[TT];

    for (int i = threadIdx.x; i < HH * TT; i += 256) {
        int k = i / 9;
        int t = i - 9 * k;
        Ws[9 * k + t + (k >> 5)] = W[i];
    }
    if (threadIdx.x < TT) bs[threadIdx.x] = bias[threadIdx.x];
    __syncthreads();

    const int lane = threadIdx.x & 31;
    const int gw0  = blockIdx.x * 8 + (threadIdx.x >> 5);
    const int nw   = gridDim.x * 8;

    float4 a0[6], a1[6];

    int rp = gw0;
    if (rp < NPAIRS) {
        // initial prefetch
        const float4* h0 = (const float4*)(hidden + (size_t)(2 * rp) * HH);
        const float4* h1 = h0 + (HH / 4);
        #pragma unroll
        for (int it = 0; it < 6; it++) {
            a0[it] = h0[it * 32 + lane];
            a1[it] = h1[it * 32 + lane];
        }
    }

    for (; rp < NPAIRS; rp += nw) {
        float acc0[TT], acc1[TT];
        #pragma unroll
        for (int t = 0; t < TT; t++) { acc0[t] = 0.f; acc1[t] = 0.f; }

        #pragma unroll
        for (int it = 0; it < 6; it++) {
            const int k4 = it * 32 + lane;
            const int wb = 36 * k4 + (k4 >> 3);
            const float hx0[4] = {a0[it].x, a0[it].y, a0[it].z, a0[it].w};
            const float hx1[4] = {a1[it].x, a1[it].y, a1[it].z, a1[it].w};
            #pragma unroll
            for (int kk = 0; kk < 4; kk++) {
                const float* wr = &Ws[wb + 9 * kk];
                const float h0v = hx0[kk];
                const float h1v = hx1[kk];
                #pragma unroll
                for (int t = 0; t < TT; t++) {
                    const float w = wr[t];
                    acc0[t] = fmaf(h0v, w, acc0[t]);
                    acc1[t] = fmaf(h1v, w, acc1[t]);
                }
            }
        }

        // rotated prefetch: issue next pair's loads before the reduce tail
        const int rpn = rp + nw;
        if (rpn < NPAIRS) {
            const float4* h0 = (const float4*)(hidden + (size_t)(2 * rpn) * HH);
            const float4* h1 = h0 + (HH / 4);
            #pragma unroll
            for (int it = 0; it < 6; it++) {
                a0[it] = h0[it * 32 + lane];
                a1[it] = h1[it * 32 + lane];
            }
        }

        // fold reduce: row A -> lanes 0-15, row B -> lanes 16-31
        float rw[TT];
        #pragma unroll
        for (int t = 0; t < TT; t++) {
            float u = acc0[t] + __shfl_xor_sync(0xffffffffu, acc0[t], 16);
            float v = acc1[t] + __shfl_xor_sync(0xffffffffu, acc1[t], 16);
            float w = (lane < 16) ? u : v;
            w += __shfl_xor_sync(0xffffffffu, w, 8);
            w += __shfl_xor_sync(0xffffffffu, w, 4);
            w += __shfl_xor_sync(0xffffffffu, w, 2);
            w += __shfl_xor_sync(0xffffffffu, w, 1);
            rw[t] = w;
        }

        float* o = logits + (size_t)(2 * rp) * TT;
        #pragma unroll
        for (int t = 0; t < TT; t++) {
            if (lane == t)       o[t]      = rw[t] + bs[t];
            if (lane == 16 + t)  o[TT + t] = rw[t] + bs[t];
        }
    }
}

// ---------------------------------------------------------------------------
// Kernel B: per-batch CRF with CHUNKED parallel scan (unchanged — working).
// ---------------------------------------------------------------------------
__global__ __launch_bounds__(800) void crf_kernel(
    const float* __restrict__ logits,
    const int*   __restrict__ mask,
    const int*   __restrict__ labels,
    const float* __restrict__ start_trans,
    const float* __restrict__ end_trans,
    const float* __restrict__ trans)
{
    __shared__ float e_s[LL * TT];
    __shared__ float ee_s[LL * TT];
    __shared__ float m_s[LL];
    __shared__ int   lab_s[LL];
    __shared__ float tr_s[TT * TT];
    __shared__ float st_s[TT];
    __shared__ float en_s[TT];
    __shared__ float M_s[NCH * TT * TT];
    __shared__ float E_s[NCH * TT];
    __shared__ float num_sh;

    const int b    = blockIdx.x;
    const int tid  = threadIdx.x;
    const int lane = tid & 31;
    const int warp = tid >> 5;

    const float L2E = 1.4426950408889634f;
    const float LN2 = 0.6931471805599453f;

    const float* lg = logits + (size_t)b * LL * TT;
    #pragma unroll 2
    for (int i = tid; i < LL * TT; i += 800) {
        float e = lg[i];
        e_s[i]  = e;
        ee_s[i] = exp2f(e * L2E);
    }
    for (int i = tid; i < LL; i += 800) {
        int l = labels[(size_t)b * LL + i];
        lab_s[i] = (l == -100) ? 0 : l;
        m_s[i]   = (float)mask[(size_t)b * LL + i];
    }
    if (tid < TT * TT) tr_s[tid] = trans[tid];
    if (tid < TT) { st_s[tid] = start_trans[tid]; en_s[tid] = end_trans[tid]; }
    __syncthreads();

    if (warp < 24) {
        const int c  = warp / 3;
        const int rg = warp % 3;
        int r = lane / 9; if (r > 2) r = 2;
        const int j = lane % 9;
        const int i = rg * 3 + r;
        const int base = r * 9;

        float et[TT];
        #pragma unroll
        for (int k = 0; k < TT; k++) et[k] = exp2f(tr_s[k * TT + j] * L2E);

        float q = (j == i) ? 1.f : 0.f;
        int   E = 0;

        const int t0 = c * CHLEN + 1;
        int t1 = t0 + CHLEN; if (t1 > LL) t1 = LL;

        float eej_next = ee_s[t0 * TT + j];
        float ms_next  = m_s[t0];

        for (int t = t0; t < t1; t++) {
            const float eej = eej_next;
            const float ms  = ms_next;
            if (t + 1 < t1) {
                eej_next = ee_s[(t + 1) * TT + j];
                ms_next  = m_s[t + 1];
            }

            float p0 = __shfl_sync(0xffffffffu, q, base + 0);
            float p1 = __shfl_sync(0xffffffffu, q, base + 1);
            float p2 = __shfl_sync(0xffffffffu, q, base + 2);
            float p3 = __shfl_sync(0xffffffffu, q, base + 3);
            float p4 = __shfl_sync(0xffffffffu, q, base + 4);
            float p5 = __shfl_sync(0xffffffffu, q, base + 5);
            float p6 = __shfl_sync(0xffffffffu, q, base + 6);
            float p7 = __shfl_sync(0xffffffffu, q, base + 7);
            float p8 = __shfl_sync(0xffffffffu, q, base + 8);

            float a  = fmaf(p1, et[1], p0 * et[0]);  a  = fmaf(p2, et[2], a);
            float b2 = fmaf(p4, et[4], p3 * et[3]);  b2 = fmaf(p5, et[5], b2);
            float cc = fmaf(p7, et[7], p6 * et[6]);  cc = fmaf(p8, et[8], cc);
            float s  = ((a + b2) + cc) * eej;

            q = (ms != 0.f) ? s : q;

            if ((t & 7) == 7) {
                float pm = fmaxf(fmaxf(fmaxf(p0, p1), fmaxf(p2, p3)),
                                 fmaxf(fmaxf(p4, p5), fmaxf(p6, p7)));
                pm = fmaxf(pm, p8);
                int ex = (__float_as_int(pm) >> 23) & 0xFF;
                float sc = __int_as_float((254 - ex) << 23);
                q *= sc;
                E += ex - 127;
            }
        }

        if (lane < 27) {
            M_s[(c * TT + i) * TT + j] = q;
            if (j == 0) E_s[c * TT + i] = (float)E;
        }
    } else {
        float acc = 0.f;
        int   msum = 0;
        for (int t = lane; t < LL; t += 32) {
            msum += (m_s[t] != 0.f) ? 1 : 0;
            if (t >= 1) {
                int lp = lab_s[t - 1], lt = lab_s[t];
                acc = fmaf(tr_s[lp * TT + lt] + e_s[t * TT + lt], m_s[t], acc);
            }
        }
        #pragma unroll
        for (int off = 16; off > 0; off >>= 1) {
            acc  += __shfl_xor_sync(0xffffffffu, acc, off);
            msum += __shfl_xor_sync(0xffffffffu, msum, off);
        }
        if (lane == 0) {
            int seq_end = msum - 1;
            if (seq_end < 0) seq_end = 0;
            int l0 = lab_s[0];
            int llast = lab_s[seq_end];
            num_sh = st_s[l0] + e_s[l0] + acc + en_s[llast];
        }
    }

    __syncthreads();

    if (warp == 0) {
        const int j = (lane < TT) ? lane : (TT - 1);

        float q  = exp2f((st_s[j] + e_s[j]) * L2E);
        int   Eq = 0;

        for (int c = 0; c < NCH; c++) {
            float Ek[TT];
            #pragma unroll
            for (int k = 0; k < TT; k++) Ek[k] = E_s[c * TT + k];
            float Em = Ek[0];
            #pragma unroll
            for (int k = 1; k < TT; k++) Em = fmaxf(Em, Ek[k]);

            float s = 0.f;
            #pragma unroll
            for (int k = 0; k < TT; k++) {
                float pk = __shfl_sync(0xffffffffu, q, k);
                float d  = Ek[k] - Em;
                float sc = (d > -120.f)
                         ? __int_as_float((((int)d) + 127) << 23) : 0.f;
                s = fmaf(pk * sc, M_s[(c * TT + k) * TT + j], s);
            }
            q  = s;
            Eq += (int)Em;

            float q0 = __shfl_sync(0xffffffffu, q, 0);
            float q1 = __shfl_sync(0xffffffffu, q, 1);
            float q2 = __shfl_sync(0xffffffffu, q, 2);
            float q3 = __shfl_sync(0xffffffffu, q, 3);
            float q4 = __shfl_sync(0xffffffffu, q, 4);
            float q5 = __shfl_sync(0xffffffffu, q, 5);
            float q6 = __shfl_sync(0xffffffffu, q, 6);
            float q7 = __shfl_sync(0xffffffffu, q, 7);
            float q8 = __shfl_sync(0xffffffffu, q, 8);
            float qm = fmaxf(fmaxf(fmaxf(q0, q1), fmaxf(q2, q3)),
                             fmaxf(fmaxf(q4, q5), fmaxf(q6, q7)));
            qm = fmaxf(qm, q8);
            int ex = (__float_as_int(qm) >> 23) & 0xFF;
            float sc2 = __int_as_float((254 - ex) << 23);
            q  *= sc2;
            Eq += ex - 127;
        }

        float v = (lane < TT) ? q * exp2f(en_s[j] * L2E) : 0.f;
        #pragma unroll
        for (int off = 16; off > 0; off >>= 1)
            v += __shfl_xor_sync(0xffffffffu, v, off);
        float denom = LN2 * (__log2f(v) + (float)Eq);

        if (lane == 0) g_llh[b] = num_sh - denom;
    }
}

// ---------------------------------------------------------------------------
// Kernel C: loss = -mean(llh), deterministic tree reduce
// ---------------------------------------------------------------------------
__global__ void loss_kernel(float* __restrict__ loss_out)
{
    int lane = threadIdx.x;   // 32 threads
    float v = g_llh[lane] + g_llh[lane + 32];
    #pragma unroll
    for (int off = 16; off > 0; off >>= 1)
        v += __shfl_xor_sync(0xffffffffu, v, off);
    if (lane == 0) loss_out[0] = -v * (1.0f / (float)BB);
}

// ---------------------------------------------------------------------------
extern "C" void kernel_launch(void* const* d_in, const int* in_sizes, int n_in,
                              void* d_out, int out_size)
{
    const float* hidden      = (const float*)d_in[0];
    const int*   attn_mask   = (const int*)d_in[1];
    const int*   labels      = (const int*)d_in[2];   // int32 (JAX x64 disabled)
    const float* W           = (const float*)d_in[3];
    const float* bias        = (const float*)d_in[4];
    const float* start_trans = (const float*)d_in[5];
    const float* end_trans   = (const float*)d_in[6];
    const float* trans       = (const float*)d_in[7];

    float* out = (float*)d_out;

    static float* scratch = nullptr;
    if (!scratch) {
        void* p = nullptr;
        cudaGetSymbolAddress(&p, g_logits_scratch);
        scratch = (float*)p;
    }

    const int NLOG = BB * LL * TT;   // 294912
    float* loss_ptr;
    float* logits_ptr;
    if (out_size >= NLOG + 1) {          // (loss, logits) concatenated
        loss_ptr   = out;
        logits_ptr = out + 1;
    } else if (out_size == NLOG) {       // logits only
        loss_ptr   = scratch;
        logits_ptr = out;
    } else {                             // loss only
        loss_ptr   = out;
        logits_ptr = scratch;
    }

    logits_kernel<<<444, 256>>>(hidden, W, bias, logits_ptr);
    crf_kernel<<<BB, 800>>>(logits_ptr, attn_mask, labels,
                            start_trans, end_trans, trans);
    loss_kernel<<<1, 32>>>(loss_ptr);
}

// round 14
// speedup vs baseline: 2.3714x; 2.3714x over previous
#include <cuda_runtime.h>
#include <cuda_bf16.h>
#include <math_constants.h>

// Problem constants (fixed shapes)
#define BB 64
#define LL 512
#define HH 768
#define TT 9
#define NROWS (BB * LL)

#define NCH 8        // chunks per sequence
#define CHLEN 64     // steps per chunk

__device__ float g_llh[BB];
__device__ float g_logits_scratch[BB * LL * TT];   // fallback if out has no room

// ---- packed f32x2 helpers (FFMA2 via PTX) ----
__device__ __forceinline__ unsigned long long pack2(float lo, float hi) {
    unsigned long long r;
    asm("mov.b64 %0, {%1, %2};" : "=l"(r) : "f"(lo), "f"(hi));
    return r;
}
__device__ __forceinline__ void unpack2(float& lo, float& hi, unsigned long long v) {
    asm("mov.b64 {%0, %1}, %2;" : "=f"(lo), "=f"(hi) : "l"(v));
}
__device__ __forceinline__ void fma2(unsigned long long& d,
                                     unsigned long long a, unsigned long long b) {
    asm("fma.rn.f32x2 %0, %1, %2, %0;" : "+l"(d) : "l"(a), "l"(b));
}

// ---------------------------------------------------------------------------
// Kernel A: logits = hidden @ W + b
// R10's schedule (grid 2048x256, one row-pair per warp, full 12x LDG.128
// prefetch) + packed-f32x2 compute:
//   W in smem as 4 packed planes Wp[tp][kk][k4] holding (w_{2tp}, w_{2tp+1})
//   and a scalar plane Ws8[kk][k4] for t=8. In-loop smem addresses are
//   base + 8*lane + compile-time const -> no ALU; LDS.64 lane stride 8B ->
//   conflict-free per 16-lane phase; LDS.32 stride 4B -> conflict-free.
//   Per (it,kk): 4 LDS.64 + 1 LDS.32 + 2 packs + 8 FFMA2 + 2 FFMA.
// Tail: fold-reduce (rowA->lanes 0-15, rowB->16-31), proven in R11/R12.
// ---------------------------------------------------------------------------
__global__ __launch_bounds__(256, 3) void logits_kernel(
    const float* __restrict__ hidden,
    const float* __restrict__ W,
    const float* __restrict__ bias,
    float* __restrict__ logits)
{
    __shared__ unsigned long long Wp[4 * 4 * 192];   // 24576 B
    __shared__ float Ws8[4 * 192];                   //  3072 B
    __shared__ float bs[TT];

    for (int k = threadIdx.x; k < HH; k += 256) {
        const float* wr = W + 9 * k;
        const int idx = (k & 3) * 192 + (k >> 2);
        Wp[idx]        = pack2(wr[0], wr[1]);
        Wp[768 + idx]  = pack2(wr[2], wr[3]);
        Wp[1536 + idx] = pack2(wr[4], wr[5]);
        Wp[2304 + idx] = pack2(wr[6], wr[7]);
        Ws8[idx]       = wr[8];
    }
    if (threadIdx.x < TT) bs[threadIdx.x] = bias[threadIdx.x];
    __syncthreads();

    const int lane = threadIdx.x & 31;
    const int rp   = blockIdx.x * 8 + (threadIdx.x >> 5);   // row pair 0..16383

    const float4* h0 = (const float4*)(hidden + (size_t)(2 * rp) * HH);
    const float4* h1 = h0 + (HH / 4);

    // full prefetch: 12 LDG.128 in flight
    float4 a0[6], a1[6];
    #pragma unroll
    for (int it = 0; it < 6; it++) {
        a0[it] = h0[it * 32 + lane];
        a1[it] = h1[it * 32 + lane];
    }

    unsigned long long A0[4] = {0ull, 0ull, 0ull, 0ull};   // row0 t-pairs
    unsigned long long A1[4] = {0ull, 0ull, 0ull, 0ull};   // row1 t-pairs
    float a0_8 = 0.f, a1_8 = 0.f;

    #pragma unroll
    for (int it = 0; it < 6; it++) {
        const float hx0[4] = {a0[it].x, a0[it].y, a0[it].z, a0[it].w};
        const float hx1[4] = {a1[it].x, a1[it].y, a1[it].z, a1[it].w};
        #pragma unroll
        for (int kk = 0; kk < 4; kk++) {
            const int idx = kk * 192 + it * 32 + lane;   // base + const
            const unsigned long long w01 = Wp[idx];
            const unsigned long long w23 = Wp[768 + idx];
            const unsigned long long w45 = Wp[1536 + idx];
            const unsigned long long w67 = Wp[2304 + idx];
            const float w8 = Ws8[idx];
            const unsigned long long h00 = pack2(hx0[kk], hx0[kk]);
            const unsigned long long h11 = pack2(hx1[kk], hx1[kk]);
            fma2(A0[0], h00, w01);
            fma2(A0[1], h00, w23);
            fma2(A0[2], h00, w45);
            fma2(A0[3], h00, w67);
            a0_8 = fmaf(hx0[kk], w8, a0_8);
            fma2(A1[0], h11, w01);
            fma2(A1[1], h11, w23);
            fma2(A1[2], h11, w45);
            fma2(A1[3], h11, w67);
            a1_8 = fmaf(hx1[kk], w8, a1_8);
        }
    }

    // unpack accumulators
    float acc0[TT], acc1[TT];
    #pragma unroll
    for (int p = 0; p < 4; p++) {
        unpack2(acc0[2 * p], acc0[2 * p + 1], A0[p]);
        unpack2(acc1[2 * p], acc1[2 * p + 1], A1[p]);
    }
    acc0[8] = a0_8;
    acc1[8] = a1_8;

    // fold reduce: row A -> lanes 0-15, row B -> lanes 16-31
    float rw[TT];
    #pragma unroll
    for (int t = 0; t < TT; t++) {
        float u = acc0[t] + __shfl_xor_sync(0xffffffffu, acc0[t], 16);
        float v = acc1[t] + __shfl_xor_sync(0xffffffffu, acc1[t], 16);
        float w = (lane < 16) ? u : v;
        w += __shfl_xor_sync(0xffffffffu, w, 8);
        w += __shfl_xor_sync(0xffffffffu, w, 4);
        w += __shfl_xor_sync(0xffffffffu, w, 2);
        w += __shfl_xor_sync(0xffffffffu, w, 1);
        rw[t] = w;
    }

    float* o = logits + (size_t)(2 * rp) * TT;
    #pragma unroll
    for (int t = 0; t < TT; t++) {
        if (lane == t)       o[t]      = rw[t] + bs[t];
        if (lane == 16 + t)  o[TT + t] = rw[t] + bs[t];
    }
}

// ---------------------------------------------------------------------------
// Kernel B: per-batch CRF with CHUNKED parallel scan (unchanged — working).
// ---------------------------------------------------------------------------
__global__ __launch_bounds__(800) void crf_kernel(
    const float* __restrict__ logits,
    const int*   __restrict__ mask,
    const int*   __restrict__ labels,
    const float* __restrict__ start_trans,
    const float* __restrict__ end_trans,
    const float* __restrict__ trans)
{
    __shared__ float e_s[LL * TT];
    __shared__ float ee_s[LL * TT];
    __shared__ float m_s[LL];
    __shared__ int   lab_s[LL];
    __shared__ float tr_s[TT * TT];
    __shared__ float st_s[TT];
    __shared__ float en_s[TT];
    __shared__ float M_s[NCH * TT * TT];
    __shared__ float E_s[NCH * TT];
    __shared__ float num_sh;

    const int b    = blockIdx.x;
    const int tid  = threadIdx.x;
    const int lane = tid & 31;
    const int warp = tid >> 5;

    const float L2E = 1.4426950408889634f;
    const float LN2 = 0.6931471805599453f;

    const float* lg = logits + (size_t)b * LL * TT;
    #pragma unroll 2
    for (int i = tid; i < LL * TT; i += 800) {
        float e = lg[i];
        e_s[i]  = e;
        ee_s[i] = exp2f(e * L2E);
    }
    for (int i = tid; i < LL; i += 800) {
        int l = labels[(size_t)b * LL + i];
        lab_s[i] = (l == -100) ? 0 : l;
        m_s[i]   = (float)mask[(size_t)b * LL + i];
    }
    if (tid < TT * TT) tr_s[tid] = trans[tid];
    if (tid < TT) { st_s[tid] = start_trans[tid]; en_s[tid] = end_trans[tid]; }
    __syncthreads();

    if (warp < 24) {
        const int c  = warp / 3;
        const int rg = warp % 3;
        int r = lane / 9; if (r > 2) r = 2;
        const int j = lane % 9;
        const int i = rg * 3 + r;
        const int base = r * 9;

        float et[TT];
        #pragma unroll
        for (int k = 0; k < TT; k++) et[k] = exp2f(tr_s[k * TT + j] * L2E);

        float q = (j == i) ? 1.f : 0.f;
        int   E = 0;

        const int t0 = c * CHLEN + 1;
        int t1 = t0 + CHLEN; if (t1 > LL) t1 = LL;

        float eej_next = ee_s[t0 * TT + j];
        float ms_next  = m_s[t0];

        for (int t = t0; t < t1; t++) {
            const float eej = eej_next;
            const float ms  = ms_next;
            if (t + 1 < t1) {
                eej_next = ee_s[(t + 1) * TT + j];
                ms_next  = m_s[t + 1];
            }

            float p0 = __shfl_sync(0xffffffffu, q, base + 0);
            float p1 = __shfl_sync(0xffffffffu, q, base + 1);
            float p2 = __shfl_sync(0xffffffffu, q, base + 2);
            float p3 = __shfl_sync(0xffffffffu, q, base + 3);
            float p4 = __shfl_sync(0xffffffffu, q, base + 4);
            float p5 = __shfl_sync(0xffffffffu, q, base + 5);
            float p6 = __shfl_sync(0xffffffffu, q, base + 6);
            float p7 = __shfl_sync(0xffffffffu, q, base + 7);
            float p8 = __shfl_sync(0xffffffffu, q, base + 8);

            float a  = fmaf(p1, et[1], p0 * et[0]);  a  = fmaf(p2, et[2], a);
            float b2 = fmaf(p4, et[4], p3 * et[3]);  b2 = fmaf(p5, et[5], b2);
            float cc = fmaf(p7, et[7], p6 * et[6]);  cc = fmaf(p8, et[8], cc);
            float s  = ((a + b2) + cc) * eej;

            q = (ms != 0.f) ? s : q;

            if ((t & 7) == 7) {
                float pm = fmaxf(fmaxf(fmaxf(p0, p1), fmaxf(p2, p3)),
                                 fmaxf(fmaxf(p4, p5), fmaxf(p6, p7)));
                pm = fmaxf(pm, p8);
                int ex = (__float_as_int(pm) >> 23) & 0xFF;
                float sc = __int_as_float((254 - ex) << 23);
                q *= sc;
                E += ex - 127;
            }
        }

        if (lane < 27) {
            M_s[(c * TT + i) * TT + j] = q;
            if (j == 0) E_s[c * TT + i] = (float)E;
        }
    } else {
        float acc = 0.f;
        int   msum = 0;
        for (int t = lane; t < LL; t += 32) {
            msum += (m_s[t] != 0.f) ? 1 : 0;
            if (t >= 1) {
                int lp = lab_s[t - 1], lt = lab_s[t];
                acc = fmaf(tr_s[lp * TT + lt] + e_s[t * TT + lt], m_s[t], acc);
            }
        }
        #pragma unroll
        for (int off = 16; off > 0; off >>= 1) {
            acc  += __shfl_xor_sync(0xffffffffu, acc, off);
            msum += __shfl_xor_sync(0xffffffffu, msum, off);
        }
        if (lane == 0) {
            int seq_end = msum - 1;
            if (seq_end < 0) seq_end = 0;
            int l0 = lab_s[0];
            int llast = lab_s[seq_end];
            num_sh = st_s[l0] + e_s[l0] + acc + en_s[llast];
        }
    }

    __syncthreads();

    if (warp == 0) {
        const int j = (lane < TT) ? lane : (TT - 1);

        float q  = exp2f((st_s[j] + e_s[j]) * L2E);
        int   Eq = 0;

        for (int c = 0; c < NCH; c++) {
            float Ek[TT];
            #pragma unroll
            for (int k = 0; k < TT; k++) Ek[k] = E_s[c * TT + k];
            float Em = Ek[0];
            #pragma unroll
            for (int k = 1; k < TT; k++) Em = fmaxf(Em, Ek[k]);

            float s = 0.f;
            #pragma unroll
            for (int k = 0; k < TT; k++) {
                float pk = __shfl_sync(0xffffffffu, q, k);
                float d  = Ek[k] - Em;
                float sc = (d > -120.f)
                         ? __int_as_float((((int)d) + 127) << 23) : 0.f;
                s = fmaf(pk * sc, M_s[(c * TT + k) * TT + j], s);
            }
            q  = s;
            Eq += (int)Em;

            float q0 = __shfl_sync(0xffffffffu, q, 0);
            float q1 = __shfl_sync(0xffffffffu, q, 1);
            float q2 = __shfl_sync(0xffffffffu, q, 2);
            float q3 = __shfl_sync(0xffffffffu, q, 3);
            float q4 = __shfl_sync(0xffffffffu, q, 4);
            float q5 = __shfl_sync(0xffffffffu, q, 5);
            float q6 = __shfl_sync(0xffffffffu, q, 6);
            float q7 = __shfl_sync(0xffffffffu, q, 7);
            float q8 = __shfl_sync(0xffffffffu, q, 8);
            float qm = fmaxf(fmaxf(fmaxf(q0, q1), fmaxf(q2, q3)),
                             fmaxf(fmaxf(q4, q5), fmaxf(q6, q7)));
            qm = fmaxf(qm, q8);
            int ex = (__float_as_int(qm) >> 23) & 0xFF;
            float sc2 = __int_as_float((254 - ex) << 23);
            q  *= sc2;
            Eq += ex - 127;
        }

        float v = (lane < TT) ? q * exp2f(en_s[j] * L2E) : 0.f;
        #pragma unroll
        for (int off = 16; off > 0; off >>= 1)
            v += __shfl_xor_sync(0xffffffffu, v, off);
        float denom = LN2 * (__log2f(v) + (float)Eq);

        if (lane == 0) g_llh[b] = num_sh - denom;
    }
}

// ---------------------------------------------------------------------------
// Kernel C: loss = -mean(llh), deterministic tree reduce
// ---------------------------------------------------------------------------
__global__ void loss_kernel(float* __restrict__ loss_out)
{
    int lane = threadIdx.x;   // 32 threads
    float v = g_llh[lane] + g_llh[lane + 32];
    #pragma unroll
    for (int off = 16; off > 0; off >>= 1)
        v += __shfl_xor_sync(0xffffffffu, v, off);
    if (lane == 0) loss_out[0] = -v * (1.0f / (float)BB);
}

// ---------------------------------------------------------------------------
extern "C" void kernel_launch(void* const* d_in, const int* in_sizes, int n_in,
                              void* d_out, int out_size)
{
    const float* hidden      = (const float*)d_in[0];
    const int*   attn_mask   = (const int*)d_in[1];
    const int*   labels      = (const int*)d_in[2];   // int32 (JAX x64 disabled)
    const float* W           = (const float*)d_in[3];
    const float* bias        = (const float*)d_in[4];
    const float* start_trans = (const float*)d_in[5];
    const float* end_trans   = (const float*)d_in[6];
    const float* trans       = (const float*)d_in[7];

    float* out = (float*)d_out;

    static float* scratch = nullptr;
    if (!scratch) {
        void* p = nullptr;
        cudaGetSymbolAddress(&p, g_logits_scratch);
        scratch = (float*)p;
    }

    const int NLOG = BB * LL * TT;   // 294912
    float* loss_ptr;
    float* logits_ptr;
    if (out_size >= NLOG + 1) {          // (loss, logits) concatenated
        loss_ptr   = out;
        logits_ptr = out + 1;
    } else if (out_size == NLOG) {       // logits only
        loss_ptr   = scratch;
        logits_ptr = out;
    } else {                             // loss only
        loss_ptr   = out;
        logits_ptr = scratch;
    }

    logits_kernel<<<2048, 256>>>(hidden, W, bias, logits_ptr);
    crf_kernel<<<BB, 800>>>(logits_ptr, attn_mask, labels,
                            start_trans, end_trans, trans);
    loss_kernel<<<1, 32>>>(loss_ptr);
}

// round 15
// speedup vs baseline: 2.7978x; 1.1798x over previous
#include <cuda_runtime.h>
#include <cuda_bf16.h>
#include <math_constants.h>

// Problem constants (fixed shapes)
#define BB 64
#define LL 512
#define HH 768
#define TT 9
#define NROWS (BB * LL)
#define NQUADS (NROWS / 4)   // 8192

#define NCH 8        // chunks per sequence
#define CHLEN 64     // steps per chunk

__device__ float g_llh[BB];
__device__ float g_logits_scratch[BB * LL * TT];   // fallback if out has no room

// ---- packed f32x2 helpers (FFMA2 via PTX) ----
__device__ __forceinline__ unsigned long long pack2(float lo, float hi) {
    unsigned long long r;
    asm("mov.b64 %0, {%1, %2};" : "=l"(r) : "f"(lo), "f"(hi));
    return r;
}
__device__ __forceinline__ void unpack2(float& lo, float& hi, unsigned long long v) {
    asm("mov.b64 {%0, %1}, %2;" : "=f"(lo), "=f"(hi) : "l"(v));
}
__device__ __forceinline__ void fma2(unsigned long long& d,
                                     unsigned long long a, unsigned long long b) {
    asm("fma.rn.f32x2 %0, %1, %2, %0;" : "+l"(d) : "l"(a), "l"(b));
}

// ---------------------------------------------------------------------------
// Kernel A: logits = hidden @ W + b
// FOUR rows per warp (grid 1024x256 = 8192 warps = 8192 row-quads): each W
// smem load is shared by 4 rows -> W-LDS traffic per row halves vs R14
// (L1 was the 74.5% wall). FFMA2 keeps FMA issue cheap: per (it,kk):
// 4 LDS.64 + 1 LDS.32 + 4 packs + 16 FFMA2 + 4 FFMA.
// 3-stage prefetch (2 its x 4 rows = 8 float4/stage); <=2 stages live ->
// ~112 regs, launch_bounds(256,2).
// ---------------------------------------------------------------------------
__global__ __launch_bounds__(256, 2) void logits_kernel(
    const float* __restrict__ hidden,
    const float* __restrict__ W,
    const float* __restrict__ bias,
    float* __restrict__ logits)
{
    __shared__ unsigned long long Wp[4 * 4 * 192];   // 24576 B
    __shared__ float Ws8[4 * 192];                   //  3072 B
    __shared__ float bs[TT];

    for (int k = threadIdx.x; k < HH; k += 256) {
        const float* wr = W + 9 * k;
        const int idx = (k & 3) * 192 + (k >> 2);
        Wp[idx]        = pack2(wr[0], wr[1]);
        Wp[768 + idx]  = pack2(wr[2], wr[3]);
        Wp[1536 + idx] = pack2(wr[4], wr[5]);
        Wp[2304 + idx] = pack2(wr[6], wr[7]);
        Ws8[idx]       = wr[8];
    }
    if (threadIdx.x < TT) bs[threadIdx.x] = bias[threadIdx.x];
    __syncthreads();

    const int lane = threadIdx.x & 31;
    const int qd   = blockIdx.x * 8 + (threadIdx.x >> 5);   // quad 0..8191

    const float4* hp = (const float4*)(hidden + (size_t)(4 * qd) * HH);
    // row r base (in float4): r * 192

    // accumulators: 4 rows x (4 packed pairs + 1 scalar)
    unsigned long long A[4][4];
    float a8[4];
    #pragma unroll
    for (int r = 0; r < 4; r++) {
        a8[r] = 0.f;
        #pragma unroll
        for (int p = 0; p < 4; p++) A[r][p] = 0ull;
    }

    float4 bufA[4][2], bufB[4][2];   // stage buffers: 4 rows x 2 its

    // prefetch stage 0 (its 0,1) and stage 1 (its 2,3): 16 LDG.128 in flight
    #pragma unroll
    for (int r = 0; r < 4; r++) {
        bufA[r][0] = hp[r * 192 + 0 * 32 + lane];
        bufA[r][1] = hp[r * 192 + 1 * 32 + lane];
    }
    #pragma unroll
    for (int r = 0; r < 4; r++) {
        bufB[r][0] = hp[r * 192 + 2 * 32 + lane];
        bufB[r][1] = hp[r * 192 + 3 * 32 + lane];
    }

    // ---- macro-ish compute for one stage (2 its) from buf, its base ib ----
    #define COMPUTE_STAGE(buf, ib)                                           \
    {                                                                        \
        _Pragma("unroll")                                                    \
        for (int ii = 0; ii < 2; ii++) {                                     \
            const int it = (ib) + ii;                                        \
            float hx[4][4];                                                  \
            _Pragma("unroll")                                                \
            for (int r = 0; r < 4; r++) {                                    \
                hx[r][0] = buf[r][ii].x; hx[r][1] = buf[r][ii].y;            \
                hx[r][2] = buf[r][ii].z; hx[r][3] = buf[r][ii].w;            \
            }                                                                \
            _Pragma("unroll")                                                \
            for (int kk = 0; kk < 4; kk++) {                                 \
                const int idx = kk * 192 + it * 32 + lane;                   \
                const unsigned long long w01 = Wp[idx];                      \
                const unsigned long long w23 = Wp[768 + idx];                \
                const unsigned long long w45 = Wp[1536 + idx];               \
                const unsigned long long w67 = Wp[2304 + idx];               \
                const float w8 = Ws8[idx];                                   \
                _Pragma("unroll")                                            \
                for (int r = 0; r < 4; r++) {                                \
                    const unsigned long long hh = pack2(hx[r][kk], hx[r][kk]); \
                    fma2(A[r][0], hh, w01);                                  \
                    fma2(A[r][1], hh, w23);                                  \
                    fma2(A[r][2], hh, w45);                                  \
                    fma2(A[r][3], hh, w67);                                  \
                    a8[r] = fmaf(hx[r][kk], w8, a8[r]);                      \
                }                                                            \
            }                                                                \
        }                                                                    \
    }

    // compute stage 0 (consumes bufA)
    COMPUTE_STAGE(bufA, 0)

    // refill bufA with stage 2 (its 4,5)
    #pragma unroll
    for (int r = 0; r < 4; r++) {
        bufA[r][0] = hp[r * 192 + 4 * 32 + lane];
        bufA[r][1] = hp[r * 192 + 5 * 32 + lane];
    }

    // compute stage 1 (bufB), then stage 2 (bufA)
    COMPUTE_STAGE(bufB, 2)
    COMPUTE_STAGE(bufA, 4)

    #undef COMPUTE_STAGE

    // unpack accumulators
    float acc[4][TT];
    #pragma unroll
    for (int r = 0; r < 4; r++) {
        #pragma unroll
        for (int p = 0; p < 4; p++)
            unpack2(acc[r][2 * p], acc[r][2 * p + 1], A[r][p]);
        acc[r][8] = a8[r];
    }

    // fold reduce: pair (0,1) -> rw01 (lanes 0-15 row0, 16-31 row1)
    //              pair (2,3) -> rw23 (lanes 0-15 row2, 16-31 row3)
    float rw01[TT], rw23[TT];
    #pragma unroll
    for (int t = 0; t < TT; t++) {
        float u = acc[0][t] + __shfl_xor_sync(0xffffffffu, acc[0][t], 16);
        float v = acc[1][t] + __shfl_xor_sync(0xffffffffu, acc[1][t], 16);
        float w = (lane < 16) ? u : v;
        w += __shfl_xor_sync(0xffffffffu, w, 8);
        w += __shfl_xor_sync(0xffffffffu, w, 4);
        w += __shfl_xor_sync(0xffffffffu, w, 2);
        w += __shfl_xor_sync(0xffffffffu, w, 1);
        rw01[t] = w;

        float u2 = acc[2][t] + __shfl_xor_sync(0xffffffffu, acc[2][t], 16);
        float v2 = acc[3][t] + __shfl_xor_sync(0xffffffffu, acc[3][t], 16);
        float w2 = (lane < 16) ? u2 : v2;
        w2 += __shfl_xor_sync(0xffffffffu, w2, 8);
        w2 += __shfl_xor_sync(0xffffffffu, w2, 4);
        w2 += __shfl_xor_sync(0xffffffffu, w2, 2);
        w2 += __shfl_xor_sync(0xffffffffu, w2, 1);
        rw23[t] = w2;
    }

    float* o = logits + (size_t)(4 * qd) * TT;
    #pragma unroll
    for (int t = 0; t < TT; t++) {
        if (lane == t) {
            o[t]          = rw01[t] + bs[t];   // row 0
            o[2 * TT + t] = rw23[t] + bs[t];   // row 2
        }
        if (lane == 16 + t) {
            o[TT + t]     = rw01[t] + bs[t];   // row 1
            o[3 * TT + t] = rw23[t] + bs[t];   // row 3
        }
    }
}

// ---------------------------------------------------------------------------
// Kernel B: per-batch CRF with CHUNKED parallel scan (unchanged — working).
// ---------------------------------------------------------------------------
__global__ __launch_bounds__(800) void crf_kernel(
    const float* __restrict__ logits,
    const int*   __restrict__ mask,
    const int*   __restrict__ labels,
    const float* __restrict__ start_trans,
    const float* __restrict__ end_trans,
    const float* __restrict__ trans)
{
    __shared__ float e_s[LL * TT];
    __shared__ float ee_s[LL * TT];
    __shared__ float m_s[LL];
    __shared__ int   lab_s[LL];
    __shared__ float tr_s[TT * TT];
    __shared__ float st_s[TT];
    __shared__ float en_s[TT];
    __shared__ float M_s[NCH * TT * TT];
    __shared__ float E_s[NCH * TT];
    __shared__ float num_sh;

    const int b    = blockIdx.x;
    const int tid  = threadIdx.x;
    const int lane = tid & 31;
    const int warp = tid >> 5;

    const float L2E = 1.4426950408889634f;
    const float LN2 = 0.6931471805599453f;

    const float* lg = logits + (size_t)b * LL * TT;
    #pragma unroll 2
    for (int i = tid; i < LL * TT; i += 800) {
        float e = lg[i];
        e_s[i]  = e;
        ee_s[i] = exp2f(e * L2E);
    }
    for (int i = tid; i < LL; i += 800) {
        int l = labels[(size_t)b * LL + i];
        lab_s[i] = (l == -100) ? 0 : l;
        m_s[i]   = (float)mask[(size_t)b * LL + i];
    }
    if (tid < TT * TT) tr_s[tid] = trans[tid];
    if (tid < TT) { st_s[tid] = start_trans[tid]; en_s[tid] = end_trans[tid]; }
    __syncthreads();

    if (warp < 24) {
        const int c  = warp / 3;
        const int rg = warp % 3;
        int r = lane / 9; if (r > 2) r = 2;
        const int j = lane % 9;
        const int i = rg * 3 + r;
        const int base = r * 9;

        float et[TT];
        #pragma unroll
        for (int k = 0; k < TT; k++) et[k] = exp2f(tr_s[k * TT + j] * L2E);

        float q = (j == i) ? 1.f : 0.f;
        int   E = 0;

        const int t0 = c * CHLEN + 1;
        int t1 = t0 + CHLEN; if (t1 > LL) t1 = LL;

        float eej_next = ee_s[t0 * TT + j];
        float ms_next  = m_s[t0];

        for (int t = t0; t < t1; t++) {
            const float eej = eej_next;
            const float ms  = ms_next;
            if (t + 1 < t1) {
                eej_next = ee_s[(t + 1) * TT + j];
                ms_next  = m_s[t + 1];
            }

            float p0 = __shfl_sync(0xffffffffu, q, base + 0);
            float p1 = __shfl_sync(0xffffffffu, q, base + 1);
            float p2 = __shfl_sync(0xffffffffu, q, base + 2);
            float p3 = __shfl_sync(0xffffffffu, q, base + 3);
            float p4 = __shfl_sync(0xffffffffu, q, base + 4);
            float p5 = __shfl_sync(0xffffffffu, q, base + 5);
            float p6 = __shfl_sync(0xffffffffu, q, base + 6);
            float p7 = __shfl_sync(0xffffffffu, q, base + 7);
            float p8 = __shfl_sync(0xffffffffu, q, base + 8);

            float a  = fmaf(p1, et[1], p0 * et[0]);  a  = fmaf(p2, et[2], a);
            float b2 = fmaf(p4, et[4], p3 * et[3]);  b2 = fmaf(p5, et[5], b2);
            float cc = fmaf(p7, et[7], p6 * et[6]);  cc = fmaf(p8, et[8], cc);
            float s  = ((a + b2) + cc) * eej;

            q = (ms != 0.f) ? s : q;

            if ((t & 7) == 7) {
                float pm = fmaxf(fmaxf(fmaxf(p0, p1), fmaxf(p2, p3)),
                                 fmaxf(fmaxf(p4, p5), fmaxf(p6, p7)));
                pm = fmaxf(pm, p8);
                int ex = (__float_as_int(pm) >> 23) & 0xFF;
                float sc = __int_as_float((254 - ex) << 23);
                q *= sc;
                E += ex - 127;
            }
        }

        if (lane < 27) {
            M_s[(c * TT + i) * TT + j] = q;
            if (j == 0) E_s[c * TT + i] = (float)E;
        }
    } else {
        float acc = 0.f;
        int   msum = 0;
        for (int t = lane; t < LL; t += 32) {
            msum += (m_s[t] != 0.f) ? 1 : 0;
            if (t >= 1) {
                int lp = lab_s[t - 1], lt = lab_s[t];
                acc = fmaf(tr_s[lp * TT + lt] + e_s[t * TT + lt], m_s[t], acc);
            }
        }
        #pragma unroll
        for (int off = 16; off > 0; off >>= 1) {
            acc  += __shfl_xor_sync(0xffffffffu, acc, off);
            msum += __shfl_xor_sync(0xffffffffu, msum, off);
        }
        if (lane == 0) {
            int seq_end = msum - 1;
            if (seq_end < 0) seq_end = 0;
            int l0 = lab_s[0];
            int llast = lab_s[seq_end];
            num_sh = st_s[l0] + e_s[l0] + acc + en_s[llast];
        }
    }

    __syncthreads();

    if (warp == 0) {
        const int j = (lane < TT) ? lane : (TT - 1);

        float q  = exp2f((st_s[j] + e_s[j]) * L2E);
        int   Eq = 0;

        for (int c = 0; c < NCH; c++) {
            float Ek[TT];
            #pragma unroll
            for (int k = 0; k < TT; k++) Ek[k] = E_s[c * TT + k];
            float Em = Ek[0];
            #pragma unroll
            for (int k = 1; k < TT; k++) Em = fmaxf(Em, Ek[k]);

            float s = 0.f;
            #pragma unroll
            for (int k = 0; k < TT; k++) {
                float pk = __shfl_sync(0xffffffffu, q, k);
                float d  = Ek[k] - Em;
                float sc = (d > -120.f)
                         ? __int_as_float((((int)d) + 127) << 23) : 0.f;
                s = fmaf(pk * sc, M_s[(c * TT + k) * TT + j], s);
            }
            q  = s;
            Eq += (int)Em;

            float q0 = __shfl_sync(0xffffffffu, q, 0);
            float q1 = __shfl_sync(0xffffffffu, q, 1);
            float q2 = __shfl_sync(0xffffffffu, q, 2);
            float q3 = __shfl_sync(0xffffffffu, q, 3);
            float q4 = __shfl_sync(0xffffffffu, q, 4);
            float q5 = __shfl_sync(0xffffffffu, q, 5);
            float q6 = __shfl_sync(0xffffffffu, q, 6);
            float q7 = __shfl_sync(0xffffffffu, q, 7);
            float q8 = __shfl_sync(0xffffffffu, q, 8);
            float qm = fmaxf(fmaxf(fmaxf(q0, q1), fmaxf(q2, q3)),
                             fmaxf(fmaxf(q4, q5), fmaxf(q6, q7)));
            qm = fmaxf(qm, q8);
            int ex = (__float_as_int(qm) >> 23) & 0xFF;
            float sc2 = __int_as_float((254 - ex) << 23);
            q  *= sc2;
            Eq += ex - 127;
        }

        float v = (lane < TT) ? q * exp2f(en_s[j] * L2E) : 0.f;
        #pragma unroll
        for (int off = 16; off > 0; off >>= 1)
            v += __shfl_xor_sync(0xffffffffu, v, off);
        float denom = LN2 * (__log2f(v) + (float)Eq);

        if (lane == 0) g_llh[b] = num_sh - denom;
    }
}

// ---------------------------------------------------------------------------
// Kernel C: loss = -mean(llh), deterministic tree reduce
// ---------------------------------------------------------------------------
__global__ void loss_kernel(float* __restrict__ loss_out)
{
    int lane = threadIdx.x;   // 32 threads
    float v = g_llh[lane] + g_llh[lane + 32];
    #pragma unroll
    for (int off = 16; off > 0; off >>= 1)
        v += __shfl_xor_sync(0xffffffffu, v, off);
    if (lane == 0) loss_out[0] = -v * (1.0f / (float)BB);
}

// ---------------------------------------------------------------------------
extern "C" void kernel_launch(void* const* d_in, const int* in_sizes, int n_in,
                              void* d_out, int out_size)
{
    const float* hidden      = (const float*)d_in[0];
    const int*   attn_mask   = (const int*)d_in[1];
    const int*   labels      = (const int*)d_in[2];   // int32 (JAX x64 disabled)
    const float* W           = (const float*)d_in[3];
    const float* bias        = (const float*)d_in[4];
    const float* start_trans = (const float*)d_in[5];
    const float* end_trans   = (const float*)d_in[6];
    const float* trans       = (const float*)d_in[7];

    float* out = (float*)d_out;

    static float* scratch = nullptr;
    if (!scratch) {
        void* p = nullptr;
        cudaGetSymbolAddress(&p, g_logits_scratch);
        scratch = (float*)p;
    }

    const int NLOG = BB * LL * TT;   // 294912
    float* loss_ptr;
    float* logits_ptr;
    if (out_size >= NLOG + 1) {          // (loss, logits) concatenated
        loss_ptr   = out;
        logits_ptr = out + 1;
    } else if (out_size == NLOG) {       // logits only
        loss_ptr   = scratch;
        logits_ptr = out;
    } else {                             // loss only
        loss_ptr   = out;
        logits_ptr = scratch;
    }

    logits_kernel<<<1024, 256>>>(hidden, W, bias, logits_ptr);
    crf_kernel<<<BB, 800>>>(logits_ptr, attn_mask, labels,
                            start_trans, end_trans, trans);
    loss_kernel<<<1, 32>>>(loss_ptr);
}

// round 16
// speedup vs baseline: 2.7997x; 1.0007x over previous
#include <cuda_runtime.h>
#include <cuda_bf16.h>
#include <math_constants.h>

// Problem constants (fixed shapes)
#define BB 64
#define LL 512
#define HH 768
#define TT 9
#define NROWS (BB * LL)
#define NQUADS (NROWS / 4)   // 8192

#define NCH 8        // chunks per sequence
#define CHLEN 64     // steps per chunk

__device__ float g_llh[BB];
__device__ float g_logits_scratch[BB * LL * TT];   // fallback if out has no room

// ---- packed f32x2 helpers (FFMA2 via PTX) ----
__device__ __forceinline__ unsigned long long pack2(float lo, float hi) {
    unsigned long long r;
    asm("mov.b64 %0, {%1, %2};" : "=l"(r) : "f"(lo), "f"(hi));
    return r;
}
__device__ __forceinline__ void unpack2(float& lo, float& hi, unsigned long long v) {
    asm("mov.b64 {%0, %1}, %2;" : "=f"(lo), "=f"(hi) : "l"(v));
}
__device__ __forceinline__ void fma2(unsigned long long& d,
                                     unsigned long long a, unsigned long long b) {
    asm("fma.rn.f32x2 %0, %1, %2, %0;" : "+l"(d) : "l"(a), "l"(b));
}

// ---------------------------------------------------------------------------
// Kernel A: logits = hidden @ W + b
// FOUR rows per warp (8192 warps = 8192 quads), FFMA2 compute, W in smem as
// packed (t,t+1) planes + scalar t=8 plane (shared by all 4 rows -> W-LDS
// amortized). R16 change: 1-it ping-pong prefetch (2x16 buf regs instead of
// 2x32) to fit 3 CTAs/SM (launch_bounds(256,3), ~82 regs) -> 24 warps/SM.
// Per (it,kk): 4 LDS.64 + 1 LDS.32 + 4 packs + 16 FFMA2 + 4 FFMA.
// ---------------------------------------------------------------------------
__global__ __launch_bounds__(256, 3) void logits_kernel(
    const float* __restrict__ hidden,
    const float* __restrict__ W,
    const float* __restrict__ bias,
    float* __restrict__ logits)
{
    __shared__ unsigned long long Wp[4 * 4 * 192];   // 24576 B
    __shared__ float Ws8[4 * 192];                   //  3072 B
    __shared__ float bs[TT];

    for (int k = threadIdx.x; k < HH; k += 256) {
        const float* wr = W + 9 * k;
        const int idx = (k & 3) * 192 + (k >> 2);
        Wp[idx]        = pack2(wr[0], wr[1]);
        Wp[768 + idx]  = pack2(wr[2], wr[3]);
        Wp[1536 + idx] = pack2(wr[4], wr[5]);
        Wp[2304 + idx] = pack2(wr[6], wr[7]);
        Ws8[idx]       = wr[8];
    }
    if (threadIdx.x < TT) bs[threadIdx.x] = bias[threadIdx.x];
    __syncthreads();

    const int lane = threadIdx.x & 31;
    const int qd   = blockIdx.x * 8 + (threadIdx.x >> 5);   // quad 0..8191

    const float4* hp = (const float4*)(hidden + (size_t)(4 * qd) * HH);
    // row r base (in float4): r * 192

    // accumulators: 4 rows x (4 packed pairs + 1 scalar)
    unsigned long long A[4][4];
    float a8[4];
    #pragma unroll
    for (int r = 0; r < 4; r++) {
        a8[r] = 0.f;
        #pragma unroll
        for (int p = 0; p < 4; p++) A[r][p] = 0ull;
    }

    float4 buf0[4], buf1[4];   // ping-pong: 4 rows x 1 it each

    // prefetch it0 -> buf0, it1 -> buf1 (8 LDG.128 in flight)
    #pragma unroll
    for (int r = 0; r < 4; r++) buf0[r] = hp[r * 192 + 0 * 32 + lane];
    #pragma unroll
    for (int r = 0; r < 4; r++) buf1[r] = hp[r * 192 + 1 * 32 + lane];

    // ---- compute one it from buf ----
    #define COMPUTE_IT(buf, it)                                              \
    {                                                                        \
        float hx[4][4];                                                      \
        _Pragma("unroll")                                                    \
        for (int r = 0; r < 4; r++) {                                        \
            hx[r][0] = buf[r].x; hx[r][1] = buf[r].y;                        \
            hx[r][2] = buf[r].z; hx[r][3] = buf[r].w;                        \
        }                                                                    \
        _Pragma("unroll")                                                    \
        for (int kk = 0; kk < 4; kk++) {                                     \
            const int idx = kk * 192 + (it) * 32 + lane;                     \
            const unsigned long long w01 = Wp[idx];                          \
            const unsigned long long w23 = Wp[768 + idx];                    \
            const unsigned long long w45 = Wp[1536 + idx];                   \
            const unsigned long long w67 = Wp[2304 + idx];                   \
            const float w8 = Ws8[idx];                                       \
            _Pragma("unroll")                                                \
            for (int r = 0; r < 4; r++) {                                    \
                const unsigned long long hh = pack2(hx[r][kk], hx[r][kk]);   \
                fma2(A[r][0], hh, w01);                                      \
                fma2(A[r][1], hh, w23);                                      \
                fma2(A[r][2], hh, w45);                                      \
                fma2(A[r][3], hh, w67);                                      \
                a8[r] = fmaf(hx[r][kk], w8, a8[r]);                          \
            }                                                                \
        }                                                                    \
    }

    #define REFILL(buf, it)                                                  \
    {                                                                        \
        _Pragma("unroll")                                                    \
        for (int r = 0; r < 4; r++) buf[r] = hp[r * 192 + (it) * 32 + lane]; \
    }

    COMPUTE_IT(buf0, 0)  REFILL(buf0, 2)
    COMPUTE_IT(buf1, 1)  REFILL(buf1, 3)
    COMPUTE_IT(buf0, 2)  REFILL(buf0, 4)
    COMPUTE_IT(buf1, 3)  REFILL(buf1, 5)
    COMPUTE_IT(buf0, 4)
    COMPUTE_IT(buf1, 5)

    #undef COMPUTE_IT
    #undef REFILL

    // unpack accumulators
    float acc[4][TT];
    #pragma unroll
    for (int r = 0; r < 4; r++) {
        #pragma unroll
        for (int p = 0; p < 4; p++)
            unpack2(acc[r][2 * p], acc[r][2 * p + 1], A[r][p]);
        acc[r][8] = a8[r];
    }

    // fold reduce: pair (0,1) -> rw01 (lanes 0-15 row0, 16-31 row1)
    //              pair (2,3) -> rw23 (lanes 0-15 row2, 16-31 row3)
    float rw01[TT], rw23[TT];
    #pragma unroll
    for (int t = 0; t < TT; t++) {
        float u = acc[0][t] + __shfl_xor_sync(0xffffffffu, acc[0][t], 16);
        float v = acc[1][t] + __shfl_xor_sync(0xffffffffu, acc[1][t], 16);
        float w = (lane < 16) ? u : v;
        w += __shfl_xor_sync(0xffffffffu, w, 8);
        w += __shfl_xor_sync(0xffffffffu, w, 4);
        w += __shfl_xor_sync(0xffffffffu, w, 2);
        w += __shfl_xor_sync(0xffffffffu, w, 1);
        rw01[t] = w;

        float u2 = acc[2][t] + __shfl_xor_sync(0xffffffffu, acc[2][t], 16);
        float v2 = acc[3][t] + __shfl_xor_sync(0xffffffffu, acc[3][t], 16);
        float w2 = (lane < 16) ? u2 : v2;
        w2 += __shfl_xor_sync(0xffffffffu, w2, 8);
        w2 += __shfl_xor_sync(0xffffffffu, w2, 4);
        w2 += __shfl_xor_sync(0xffffffffu, w2, 2);
        w2 += __shfl_xor_sync(0xffffffffu, w2, 1);
        rw23[t] = w2;
    }

    float* o = logits + (size_t)(4 * qd) * TT;
    #pragma unroll
    for (int t = 0; t < TT; t++) {
        if (lane == t) {
            o[t]          = rw01[t] + bs[t];   // row 0
            o[2 * TT + t] = rw23[t] + bs[t];   // row 2
        }
        if (lane == 16 + t) {
            o[TT + t]     = rw01[t] + bs[t];   // row 1
            o[3 * TT + t] = rw23[t] + bs[t];   // row 3
        }
    }
}

// ---------------------------------------------------------------------------
// Kernel B: per-batch CRF with CHUNKED parallel scan (unchanged — working).
// ---------------------------------------------------------------------------
__global__ __launch_bounds__(800) void crf_kernel(
    const float* __restrict__ logits,
    const int*   __restrict__ mask,
    const int*   __restrict__ labels,
    const float* __restrict__ start_trans,
    const float* __restrict__ end_trans,
    const float* __restrict__ trans)
{
    __shared__ float e_s[LL * TT];
    __shared__ float ee_s[LL * TT];
    __shared__ float m_s[LL];
    __shared__ int   lab_s[LL];
    __shared__ float tr_s[TT * TT];
    __shared__ float st_s[TT];
    __shared__ float en_s[TT];
    __shared__ float M_s[NCH * TT * TT];
    __shared__ float E_s[NCH * TT];
    __shared__ float num_sh;

    const int b    = blockIdx.x;
    const int tid  = threadIdx.x;
    const int lane = tid & 31;
    const int warp = tid >> 5;

    const float L2E = 1.4426950408889634f;
    const float LN2 = 0.6931471805599453f;

    const float* lg = logits + (size_t)b * LL * TT;
    #pragma unroll 2
    for (int i = tid; i < LL * TT; i += 800) {
        float e = lg[i];
        e_s[i]  = e;
        ee_s[i] = exp2f(e * L2E);
    }
    for (int i = tid; i < LL; i += 800) {
        int l = labels[(size_t)b * LL + i];
        lab_s[i] = (l == -100) ? 0 : l;
        m_s[i]   = (float)mask[(size_t)b * LL + i];
    }
    if (tid < TT * TT) tr_s[tid] = trans[tid];
    if (tid < TT) { st_s[tid] = start_trans[tid]; en_s[tid] = end_trans[tid]; }
    __syncthreads();

    if (warp < 24) {
        const int c  = warp / 3;
        const int rg = warp % 3;
        int r = lane / 9; if (r > 2) r = 2;
        const int j = lane % 9;
        const int i = rg * 3 + r;
        const int base = r * 9;

        float et[TT];
        #pragma unroll
        for (int k = 0; k < TT; k++) et[k] = exp2f(tr_s[k * TT + j] * L2E);

        float q = (j == i) ? 1.f : 0.f;
        int   E = 0;

        const int t0 = c * CHLEN + 1;
        int t1 = t0 + CHLEN; if (t1 > LL) t1 = LL;

        float eej_next = ee_s[t0 * TT + j];
        float ms_next  = m_s[t0];

        for (int t = t0; t < t1; t++) {
            const float eej = eej_next;
            const float ms  = ms_next;
            if (t + 1 < t1) {
                eej_next = ee_s[(t + 1) * TT + j];
                ms_next  = m_s[t + 1];
            }

            float p0 = __shfl_sync(0xffffffffu, q, base + 0);
            float p1 = __shfl_sync(0xffffffffu, q, base + 1);
            float p2 = __shfl_sync(0xffffffffu, q, base + 2);
            float p3 = __shfl_sync(0xffffffffu, q, base + 3);
            float p4 = __shfl_sync(0xffffffffu, q, base + 4);
            float p5 = __shfl_sync(0xffffffffu, q, base + 5);
            float p6 = __shfl_sync(0xffffffffu, q, base + 6);
            float p7 = __shfl_sync(0xffffffffu, q, base + 7);
            float p8 = __shfl_sync(0xffffffffu, q, base + 8);

            float a  = fmaf(p1, et[1], p0 * et[0]);  a  = fmaf(p2, et[2], a);
            float b2 = fmaf(p4, et[4], p3 * et[3]);  b2 = fmaf(p5, et[5], b2);
            float cc = fmaf(p7, et[7], p6 * et[6]);  cc = fmaf(p8, et[8], cc);
            float s  = ((a + b2) + cc) * eej;

            q = (ms != 0.f) ? s : q;

            if ((t & 7) == 7) {
                float pm = fmaxf(fmaxf(fmaxf(p0, p1), fmaxf(p2, p3)),
                                 fmaxf(fmaxf(p4, p5), fmaxf(p6, p7)));
                pm = fmaxf(pm, p8);
                int ex = (__float_as_int(pm) >> 23) & 0xFF;
                float sc = __int_as_float((254 - ex) << 23);
                q *= sc;
                E += ex - 127;
            }
        }

        if (lane < 27) {
            M_s[(c * TT + i) * TT + j] = q;
            if (j == 0) E_s[c * TT + i] = (float)E;
        }
    } else {
        float acc = 0.f;
        int   msum = 0;
        for (int t = lane; t < LL; t += 32) {
            msum += (m_s[t] != 0.f) ? 1 : 0;
            if (t >= 1) {
                int lp = lab_s[t - 1], lt = lab_s[t];
                acc = fmaf(tr_s[lp * TT + lt] + e_s[t * TT + lt], m_s[t], acc);
            }
        }
        #pragma unroll
        for (int off = 16; off > 0; off >>= 1) {
            acc  += __shfl_xor_sync(0xffffffffu, acc, off);
            msum += __shfl_xor_sync(0xffffffffu, msum, off);
        }
        if (lane == 0) {
            int seq_end = msum - 1;
            if (seq_end < 0) seq_end = 0;
            int l0 = lab_s[0];
            int llast = lab_s[seq_end];
            num_sh = st_s[l0] + e_s[l0] + acc + en_s[llast];
        }
    }

    __syncthreads();

    if (warp == 0) {
        const int j = (lane < TT) ? lane : (TT - 1);

        float q  = exp2f((st_s[j] + e_s[j]) * L2E);
        int   Eq = 0;

        for (int c = 0; c < NCH; c++) {
            float Ek[TT];
            #pragma unroll
            for (int k = 0; k < TT; k++) Ek[k] = E_s[c * TT + k];
            float Em = Ek[0];
            #pragma unroll
            for (int k = 1; k < TT; k++) Em = fmaxf(Em, Ek[k]);

            float s = 0.f;
            #pragma unroll
            for (int k = 0; k < TT; k++) {
                float pk = __shfl_sync(0xffffffffu, q, k);
                float d  = Ek[k] - Em;
                float sc = (d > -120.f)
                         ? __int_as_float((((int)d) + 127) << 23) : 0.f;
                s = fmaf(pk * sc, M_s[(c * TT + k) * TT + j], s);
            }
            q  = s;
            Eq += (int)Em;

            float q0 = __shfl_sync(0xffffffffu, q, 0);
            float q1 = __shfl_sync(0xffffffffu, q, 1);
            float q2 = __shfl_sync(0xffffffffu, q, 2);
            float q3 = __shfl_sync(0xffffffffu, q, 3);
            float q4 = __shfl_sync(0xffffffffu, q, 4);
            float q5 = __shfl_sync(0xffffffffu, q, 5);
            float q6 = __shfl_sync(0xffffffffu, q, 6);
            float q7 = __shfl_sync(0xffffffffu, q, 7);
            float q8 = __shfl_sync(0xffffffffu, q, 8);
            float qm = fmaxf(fmaxf(fmaxf(q0, q1), fmaxf(q2, q3)),
                             fmaxf(fmaxf(q4, q5), fmaxf(q6, q7)));
            qm = fmaxf(qm, q8);
            int ex = (__float_as_int(qm) >> 23) & 0xFF;
            float sc2 = __int_as_float((254 - ex) << 23);
            q  *= sc2;
            Eq += ex - 127;
        }

        float v = (lane < TT) ? q * exp2f(en_s[j] * L2E) : 0.f;
        #pragma unroll
        for (int off = 16; off > 0; off >>= 1)
            v += __shfl_xor_sync(0xffffffffu, v, off);
        float denom = LN2 * (__log2f(v) + (float)Eq);

        if (lane == 0) g_llh[b] = num_sh - denom;
    }
}

// ---------------------------------------------------------------------------
// Kernel C: loss = -mean(llh), deterministic tree reduce
// ---------------------------------------------------------------------------
__global__ void loss_kernel(float* __restrict__ loss_out)
{
    int lane = threadIdx.x;   // 32 threads
    float v = g_llh[lane] + g_llh[lane + 32];
    #pragma unroll
    for (int off = 16; off > 0; off >>= 1)
        v += __shfl_xor_sync(0xffffffffu, v, off);
    if (lane == 0) loss_out[0] = -v * (1.0f / (float)BB);
}

// ---------------------------------------------------------------------------
extern "C" void kernel_launch(void* const* d_in, const int* in_sizes, int n_in,
                              void* d_out, int out_size)
{
    const float* hidden      = (const float*)d_in[0];
    const int*   attn_mask   = (const int*)d_in[1];
    const int*   labels      = (const int*)d_in[2];   // int32 (JAX x64 disabled)
    const float* W           = (const float*)d_in[3];
    const float* bias        = (const float*)d_in[4];
    const float* start_trans = (const float*)d_in[5];
    const float* end_trans   = (const float*)d_in[6];
    const float* trans       = (const float*)d_in[7];

    float* out = (float*)d_out;

    static float* scratch = nullptr;
    if (!scratch) {
        void* p = nullptr;
        cudaGetSymbolAddress(&p, g_logits_scratch);
        scratch = (float*)p;
    }

    const int NLOG = BB * LL * TT;   // 294912
    float* loss_ptr;
    float* logits_ptr;
    if (out_size >= NLOG + 1) {          // (loss, logits) concatenated
        loss_ptr   = out;
        logits_ptr = out + 1;
    } else if (out_size == NLOG) {       // logits only
        loss_ptr   = scratch;
        logits_ptr = out;
    } else {                             // loss only
        loss_ptr   = out;
        logits_ptr = scratch;
    }

    logits_kernel<<<1024, 256>>>(hidden, W, bias, logits_ptr);
    crf_kernel<<<BB, 800>>>(logits_ptr, attn_mask, labels,
                            start_trans, end_trans, trans);
    loss_kernel<<<1, 32>>>(loss_ptr);
}